// round 2
// baseline (speedup 1.0000x reference)
#include <cuda_runtime.h>

// Problem constants
#define Bc    4096
#define Tc    256
#define I1c   38
#define H1c   50
#define H2c   15
#define NCc   14

// Tiling
#define NB    28            // batch elems per CTA
#define NTH   288           // threads per CTA (9 warps)
#define NJOB  260           // 200 L1 gate rows + 60 L2 gate rows
#define KLEN1 88            // dot length for L1 rows (38 + 50)
#define KLEN2 65            // dot length for L2 rows (50 + 15)
#define VROWS 128           // v rows padded (38+50+15=103 -> 128, pad zeros)
#define VP    28            // v pitch (floats)
#define VSZ   (VROWS*VP)    // 3584 floats per buffer
#define GP    29            // gate staging pitch (odd -> conflict-free STS)
#define WTS   288           // weight table stride

// Shared memory layout (floats)
#define SM_WT 0
#define SM_V  (KLEN1*WTS)          // 25344
#define SM_G  (SM_V + 2*VSZ)       // 32512
#define SMEM_FLOATS (SM_G + NJOB*GP)   // 40052
#define SMEM_BYTES  (SMEM_FLOATS*4)    // 160208 B

__device__ __forceinline__ float sigf(float x){
    float e = __expf(-x);                       // MUFU.EX2 path, ~2 ulp
    return __fdividef(1.0f, 1.0f + e);          // MUFU.RCP path
}
__device__ __forceinline__ float tanh_(float x){
    float a = fabsf(x);
    float e = __expf(-2.0f * a);                // e in (0,1], no overflow
    float r = __fdividef(1.0f - e, 1.0f + e);
    return copysignf(r, x);
}

__global__ __launch_bounds__(NTH, 1)
void lstm_persist_kernel(const float* __restrict__ x,
                         const float* __restrict__ w_ih1, const float* __restrict__ w_hh1,
                         const float* __restrict__ b_ih1, const float* __restrict__ b_hh1,
                         const float* __restrict__ w_ih2, const float* __restrict__ w_hh2,
                         const float* __restrict__ b_ih2, const float* __restrict__ b_hh2,
                         const float* __restrict__ w_fc,  const float* __restrict__ b_fc,
                         float* __restrict__ out)
{
    extern __shared__ float sm[];
    float* wT = sm + SM_WT;   // [88][288] padded transposed weights
    float* vb = sm + SM_V;    // [2][128][28] value vector, double buffered
    float* gb = sm + SM_G;    // [260][29] gate staging

    const int tid = threadIdx.x;
    const int b0  = blockIdx.x * NB;

    // ---- Build unified weight table: column tid = this thread's gate row ----
    // v index space: [0..38) = x, [38..88) = h1, [88..103) = h2 (rows 103..127 zero)
    // L1 rows (j<200): window base 0, weights [w_ih1 | w_hh1]
    // L2 rows (200<=j<260): window base 38, weights [w_ih2 | w_hh2 | zero-pad]
    for (int k = 0; k < KLEN1; k++){
        float w = 0.0f;
        if (tid < 200){
            w = (k < I1c) ? w_ih1[tid*I1c + k]
                          : w_hh1[tid*H1c + (k - I1c)];
        } else if (tid < NJOB){
            int r = tid - 200;
            if (k < H1c)            w = w_ih2[r*H1c + k];
            else if (k < H1c + H2c) w = w_hh2[r*H2c + (k - H1c)];
        }
        wT[k*WTS + tid] = w;
    }
    float bias = 0.0f;
    if (tid < 200)       bias = b_ih1[tid] + b_hh1[tid];
    else if (tid < NJOB) bias = b_ih2[tid-200] + b_hh2[tid-200];

    // ---- Zero both v buffers (also zeroes padding rows), then load x(0) ----
    for (int idx = tid; idx < 2*VSZ; idx += NTH) vb[idx] = 0.0f;
    __syncthreads();
    for (int idx = tid; idx < NB*I1c; idx += NTH){
        int nb = idx / I1c, i = idx % I1c;
        int b = b0 + nb;
        if (b < Bc) vb[i*VP + nb] = x[((size_t)b * Tc) * I1c + i];
    }

    // Cell state: slot s of this thread owns unit u = tid + s*288 (u < 1820)
    float cst[7];
    #pragma unroll
    for (int s = 0; s < 7; s++) cst[s] = 0.0f;
    __syncthreads();

    const int base = (tid < 200) ? 0 : I1c;   // v-window base for this gate row

    // Iterations t = 0..Tc. At iter t: L1 computes step t (x(t), h1(t-1)),
    // L2 computes step t-1 (h1(t-1), h2(t-2)). Iter Tc drains L2's final step.
    for (int t = 0; t <= Tc; t++){
        const int cur = t & 1;
        float* vc = vb + cur * VSZ;
        float* vn = vb + (cur ^ 1) * VSZ;

        // ---------------- Phase A: all gate dot products ----------------
        if (tid < NJOB){
            float4 acc[7];
            #pragma unroll
            for (int q = 0; q < 7; q++){
                acc[q].x = bias; acc[q].y = bias; acc[q].z = bias; acc[q].w = bias;
            }
            const float* vrow = vc + base * VP;
            #pragma unroll 4
            for (int k = 0; k < KLEN2; k++){
                float w = wT[k*WTS + tid];
                const float4* vr = reinterpret_cast<const float4*>(vrow + k*VP);
                #pragma unroll
                for (int q = 0; q < 7; q++){
                    float4 vv = vr[q];
                    acc[q].x = fmaf(w, vv.x, acc[q].x);
                    acc[q].y = fmaf(w, vv.y, acc[q].y);
                    acc[q].z = fmaf(w, vv.z, acc[q].z);
                    acc[q].w = fmaf(w, vv.w, acc[q].w);
                }
            }
            if (tid < 224){   // warps 0-6: L1 rows (and warp-6 L2 rows use zero-pad wT)
                #pragma unroll 4
                for (int k = KLEN2; k < KLEN1; k++){
                    float w = wT[k*WTS + tid];
                    const float4* vr = reinterpret_cast<const float4*>(vrow + k*VP);
                    #pragma unroll
                    for (int q = 0; q < 7; q++){
                        float4 vv = vr[q];
                        acc[q].x = fmaf(w, vv.x, acc[q].x);
                        acc[q].y = fmaf(w, vv.y, acc[q].y);
                        acc[q].z = fmaf(w, vv.z, acc[q].z);
                        acc[q].w = fmaf(w, vv.w, acc[q].w);
                    }
                }
            }
            float* gr = gb + tid * GP;
            #pragma unroll
            for (int q = 0; q < 7; q++){
                gr[q*4+0] = acc[q].x; gr[q*4+1] = acc[q].y;
                gr[q*4+2] = acc[q].z; gr[q*4+3] = acc[q].w;
            }
        } else {
            // threads 260..287: prefetch x(t+1) into next buffer during compute
            int nb = tid - NJOB;
            int b = b0 + nb;
            if (t + 1 < Tc && b < Bc){
                const float* xs = x + ((size_t)b * Tc + (t + 1)) * I1c;
                #pragma unroll
                for (int i = 0; i < I1c; i++) vn[i*VP + nb] = __ldg(xs + i);
            }
        }
        __syncthreads();

        // ---------------- Phase B: cell updates ----------------
        #pragma unroll
        for (int s = 0; s < 7; s++){
            int u = tid + s * NTH;
            if (u >= 1820) break;                 // 1400 L1 units + 420 L2 units
            if (u < 1400){
                int h = u / NB, nb = u % NB;
                float gI = gb[(h        )*GP + nb];
                float gF = gb[(H1c   + h)*GP + nb];
                float gG = gb[(2*H1c + h)*GP + nb];
                float gO = gb[(3*H1c + h)*GP + nb];
                float c = fmaf(sigf(gF), cst[s], sigf(gI) * tanh_(gG));
                cst[s] = c;
                vn[(I1c + h)*VP + nb] = sigf(gO) * tanh_(c);
            } else if (t >= 1){                   // L2 step t-1 exists only for t>=1
                int r = (u - 1400) / NB, nb = (u - 1400) % NB;
                float gI = gb[(200 + r)*GP + nb];
                float gF = gb[(215 + r)*GP + nb];
                float gG = gb[(230 + r)*GP + nb];
                float gO = gb[(245 + r)*GP + nb];
                float c = fmaf(sigf(gF), cst[s], sigf(gI) * tanh_(gG));
                cst[s] = c;
                vn[(88 + r)*VP + nb] = sigf(gO) * tanh_(c);
            }
        }
        __syncthreads();
    }

    // ---- FC head: out[b] = h2(T-1) @ w_fc^T + b_fc ----
    // Last iter t=Tc has cur=0, so final h2 lives in buffer 1.
    const float* vf = vb + VSZ;
    for (int u = tid; u < NB * NCc; u += NTH){
        int nb = u / NCc, cls = u % NCc;
        int b = b0 + nb;
        if (b < Bc){
            float s = b_fc[cls];
            #pragma unroll
            for (int h = 0; h < H2c; h++)
                s = fmaf(w_fc[cls*H2c + h], vf[(88 + h)*VP + nb], s);
            out[b*NCc + cls] = s;
        }
    }
}

extern "C" void kernel_launch(void* const* d_in, const int* in_sizes, int n_in,
                              void* d_out, int out_size)
{
    const float* x     = (const float*)d_in[0];
    const float* w_ih1 = (const float*)d_in[1];
    const float* w_hh1 = (const float*)d_in[2];
    const float* b_ih1 = (const float*)d_in[3];
    const float* b_hh1 = (const float*)d_in[4];
    const float* w_ih2 = (const float*)d_in[5];
    const float* w_hh2 = (const float*)d_in[6];
    const float* b_ih2 = (const float*)d_in[7];
    const float* b_hh2 = (const float*)d_in[8];
    const float* w_fc  = (const float*)d_in[9];
    const float* b_fc  = (const float*)d_in[10];
    float* out = (float*)d_out;

    cudaFuncSetAttribute(lstm_persist_kernel,
                         cudaFuncAttributeMaxDynamicSharedMemorySize, SMEM_BYTES);

    const int grid = (Bc + NB - 1) / NB;   // 147 CTAs -> one wave on 148 SMs
    lstm_persist_kernel<<<grid, NTH, SMEM_BYTES>>>(
        x, w_ih1, w_hh1, b_ih1, b_hh1,
        w_ih2, w_hh2, b_ih2, b_hh2, w_fc, b_fc, out);
}

// round 3
// speedup vs baseline: 1.0419x; 1.0419x over previous
#include <cuda_runtime.h>

// Problem constants
#define Bc 4096
#define Tc 256
#define I1c 38
#define H1c 50
#define H2c 15
#define NCc 14

// Tiling
#define NB   32            // batch elems per CTA
#define NTH  288           // 9 warps: warps 0-7 = units 0..63 x 4 colgroups, warp 8 special
#define NU   65            // unit-groups: 50 L1 units + 15 L2 units
#define KL   88            // padded dot length (38+50); L2 uses window base 38 + zero pad
#define KL2  65            // real dot length for L2 (50+15)
#define VP   32            // value-vector pitch (floats) = 128 B
#define VROWS 128          // rows: [0,38)=x, [38,88)=h1, [88,103)=h2, rest zero pad
#define VSZ  (VROWS*VP)    // 4096 floats per buffer

// Shared memory: wP[(k*4+g)*65+u] = (w,w) packed u64, then v[2][128][32] floats
#define WP_U64   (KL*4*NU)            // 22880 u64 = 183040 B
#define SM_V_OFF (WP_U64*8)           // byte offset of v
#define SMEM_BYTES (SM_V_OFF + 2*VSZ*4)   // 215808 B

typedef unsigned long long u64t;

__device__ __forceinline__ u64t pk2(float a, float b){
    u64t d; asm("mov.b64 %0, {%1, %2};" : "=l"(d) : "f"(a), "f"(b)); return d;
}
__device__ __forceinline__ void up2(u64t d, float& a, float& b){
    asm("mov.b64 {%0, %1}, %2;" : "=f"(a), "=f"(b) : "l"(d));
}
__device__ __forceinline__ void fma2(u64t& d, u64t a, u64t b){
    asm("fma.rn.f32x2 %0, %1, %2, %0;" : "+l"(d) : "l"(a), "l"(b));
}

__device__ __forceinline__ float sigf(float x){
    float e = __expf(-x);
    return __fdividef(1.0f, 1.0f + e);
}
__device__ __forceinline__ float tanh_(float x){
    float a = fabsf(x);
    float e = __expf(-2.0f * a);
    float r = __fdividef(1.0f - e, 1.0f + e);
    return copysignf(r, x);
}

__global__ __launch_bounds__(NTH, 1)
void lstm_persist_kernel(const float* __restrict__ x,
                         const float* __restrict__ w_ih1, const float* __restrict__ w_hh1,
                         const float* __restrict__ b_ih1, const float* __restrict__ b_hh1,
                         const float* __restrict__ w_ih2, const float* __restrict__ w_hh2,
                         const float* __restrict__ b_ih2, const float* __restrict__ b_hh2,
                         const float* __restrict__ w_fc,  const float* __restrict__ b_fc,
                         float* __restrict__ out)
{
    extern __shared__ float sm[];
    u64t*  wp   = reinterpret_cast<u64t*>(sm);
    float* vbuf = sm + SM_V_OFF / 4;

    const int tid = threadIdx.x;
    const int b0  = blockIdx.x * NB;

    // ---- Build duplicated weight table: wp[(k*4+g)*NU + u] = (w,w) ----
    for (int idx = tid; idx < WP_U64; idx += NTH){
        int u  = idx % NU;
        int kg = idx / NU;
        int g  = kg & 3, k = kg >> 2;
        float w = 0.0f;
        if (u < 50){                       // L1 unit u, window base 0: [x | h1]
            int row = g * H1c + u;
            w = (k < I1c) ? w_ih1[row*I1c + k] : w_hh1[row*H1c + (k - I1c)];
        } else {                           // L2 unit r, window base 38: [h1 | h2 | pad]
            int r = u - 50, row = g * H2c + r;
            if (k < H1c)            w = w_ih2[row*H1c + k];
            else if (k < KL2)       w = w_hh2[row*H2c + (k - H1c)];
        }
        wp[idx] = pk2(w, w);
    }

    // ---- Zero both v buffers (includes pad rows), then load x(0) ----
    for (int idx = tid; idx < 2*VSZ; idx += NTH) vbuf[idx] = 0.0f;
    __syncthreads();
    for (int idx = tid; idx < NB*I1c; idx += NTH){
        int nb = idx / I1c, i = idx % I1c;
        vbuf[i*VP + nb] = x[((size_t)(b0 + nb) * Tc) * I1c + i];
    }

    // Per-thread roles
    const int u  = tid >> 2;        // unit group (tid<256)
    const int cg = tid & 3;         // batch colgroup (8 batch each)
    const bool isL1 = (u < 50);

    float bias[4];
    if (tid < 256){
        if (isL1){
            #pragma unroll
            for (int g = 0; g < 4; g++) bias[g] = b_ih1[g*H1c + u] + b_hh1[g*H1c + u];
        } else {
            int r = u - 50;
            #pragma unroll
            for (int g = 0; g < 4; g++) bias[g] = b_ih2[g*H2c + r] + b_hh2[g*H2c + r];
        }
    }
    // Warp 8: lane j handles L2 unit 14 for batch j (scalar), plus x prefetch
    float b14[4];
    if (tid >= 256){
        #pragma unroll
        for (int g = 0; g < 4; g++) b14[g] = b_ih2[g*H2c + 14] + b_hh2[g*H2c + 14];
    }

    float cst[8];
    #pragma unroll
    for (int s = 0; s < 8; s++) cst[s] = 0.0f;
    float c14 = 0.0f;

    const int base = isL1 ? 0 : I1c;
    __syncthreads();

    // Iter t: L1 computes step t (reads x(t), h1(t-1)); L2 computes step t-1
    // (reads h1(t-1), h2(t-2)). All writes go to the other buffer vn.
    for (int t = 0; t <= Tc; t++){
        float* vc = vbuf + (t & 1) * VSZ;
        float* vn = vbuf + ((t + 1) & 1) * VSZ;

        if (tid < 256){
            if (isL1 ? (t < Tc) : true){
                u64t acc[4][4];
                #pragma unroll
                for (int g = 0; g < 4; g++)
                    #pragma unroll
                    for (int p = 0; p < 4; p++) acc[g][p] = pk2(bias[g], bias[g]);

                const u64t* vrow = reinterpret_cast<const u64t*>(vc + base*VP) + cg*4;
                const u64t* wrow = wp + u;
                #pragma unroll 4
                for (int k = 0; k < KL; k++){
                    ulonglong2 p0 = *reinterpret_cast<const ulonglong2*>(vrow + (size_t)k*(VP/2));
                    ulonglong2 p1 = *reinterpret_cast<const ulonglong2*>(vrow + (size_t)k*(VP/2) + 2);
                    u64t w0 = wrow[(k*4+0)*NU];
                    u64t w1 = wrow[(k*4+1)*NU];
                    u64t w2 = wrow[(k*4+2)*NU];
                    u64t w3 = wrow[(k*4+3)*NU];
                    fma2(acc[0][0], w0, p0.x); fma2(acc[0][1], w0, p0.y);
                    fma2(acc[0][2], w0, p1.x); fma2(acc[0][3], w0, p1.y);
                    fma2(acc[1][0], w1, p0.x); fma2(acc[1][1], w1, p0.y);
                    fma2(acc[1][2], w1, p1.x); fma2(acc[1][3], w1, p1.y);
                    fma2(acc[2][0], w2, p0.x); fma2(acc[2][1], w2, p0.y);
                    fma2(acc[2][2], w2, p1.x); fma2(acc[2][3], w2, p1.y);
                    fma2(acc[3][0], w3, p0.x); fma2(acc[3][1], w3, p0.y);
                    fma2(acc[3][2], w3, p1.x); fma2(acc[3][3], w3, p1.y);
                }

                if (isL1 || t >= 1){    // L2's step t-1 exists only for t>=1
                    float* hout = isL1 ? (vn + (I1c + u)*VP + cg*8)
                                       : (vn + (88 + (u - 50))*VP + cg*8);
                    #pragma unroll
                    for (int p = 0; p < 4; p++){
                        float i0,i1,f0,f1,g0,g1,o0,o1;
                        up2(acc[0][p], i0, i1);
                        up2(acc[1][p], f0, f1);
                        up2(acc[2][p], g0, g1);
                        up2(acc[3][p], o0, o1);
                        float c0 = fmaf(sigf(f0), cst[2*p  ], sigf(i0)*tanh_(g0));
                        float c1 = fmaf(sigf(f1), cst[2*p+1], sigf(i1)*tanh_(g1));
                        cst[2*p  ] = c0;
                        cst[2*p+1] = c1;
                        hout[2*p  ] = sigf(o0)*tanh_(c0);
                        hout[2*p+1] = sigf(o1)*tanh_(c1);
                    }
                }
            }
        } else {
            // ---- Warp 8: scalar path for L2 unit 14, then x(t+1) prefetch ----
            int j = tid - 256;     // batch index 0..31
            float a0 = b14[0], a1 = b14[1], a2 = b14[2], a3 = b14[3];
            const float* vr  = vc + I1c*VP + j;
            const float* wpf = reinterpret_cast<const float*>(wp);   // lower half of (w,w)
            #pragma unroll 5
            for (int k = 0; k < KL2; k++){
                float v = vr[k*VP];
                a0 = fmaf(wpf[((k*4+0)*NU + 64)*2], v, a0);
                a1 = fmaf(wpf[((k*4+1)*NU + 64)*2], v, a1);
                a2 = fmaf(wpf[((k*4+2)*NU + 64)*2], v, a2);
                a3 = fmaf(wpf[((k*4+3)*NU + 64)*2], v, a3);
            }
            if (t >= 1){
                c14 = fmaf(sigf(a1), c14, sigf(a0)*tanh_(a2));
                vn[(88 + 14)*VP + j] = sigf(a3)*tanh_(c14);
            }
            if (t + 1 < Tc){
                const float* xs = x + ((size_t)(b0 + j) * Tc + (t + 1)) * I1c;
                float* xd = vn + j;
                #pragma unroll
                for (int i = 0; i < I1c; i++) xd[i*VP] = __ldcg(xs + i);
            }
        }
        __syncthreads();
    }

    // ---- FC head: final h2 lives in vbuf[1] rows 88..102 ----
    const float* h2f = vbuf + VSZ + 88*VP;
    for (int q = tid; q < NB*NCc; q += NTH){
        int nb = q / NCc, cls = q % NCc;
        float s = b_fc[cls];
        #pragma unroll
        for (int h = 0; h < H2c; h++)
            s = fmaf(w_fc[cls*H2c + h], h2f[h*VP + nb], s);
        out[(size_t)(b0 + nb)*NCc + cls] = s;
    }
}

extern "C" void kernel_launch(void* const* d_in, const int* in_sizes, int n_in,
                              void* d_out, int out_size)
{
    const float* x     = (const float*)d_in[0];
    const float* w_ih1 = (const float*)d_in[1];
    const float* w_hh1 = (const float*)d_in[2];
    const float* b_ih1 = (const float*)d_in[3];
    const float* b_hh1 = (const float*)d_in[4];
    const float* w_ih2 = (const float*)d_in[5];
    const float* w_hh2 = (const float*)d_in[6];
    const float* b_ih2 = (const float*)d_in[7];
    const float* b_hh2 = (const float*)d_in[8];
    const float* w_fc  = (const float*)d_in[9];
    const float* b_fc  = (const float*)d_in[10];
    float* out = (float*)d_out;

    cudaFuncSetAttribute(lstm_persist_kernel,
                         cudaFuncAttributeMaxDynamicSharedMemorySize, SMEM_BYTES);

    const int grid = Bc / NB;   // 128 CTAs -> one wave
    lstm_persist_kernel<<<grid, NTH, SMEM_BYTES>>>(
        x, w_ih1, w_hh1, b_ih1, b_hh1,
        w_ih2, w_hh2, b_ih2, b_hh2, w_fc, b_fc, out);
}

// round 5
// speedup vs baseline: 1.0420x; 1.0001x over previous
#include <cuda_runtime.h>

// Problem constants
#define Bc 4096
#define Tc 256
#define I1c 38
#define H1c 50
#define H2c 15
#define NCc 14

// Tiling
#define NB   32            // batch elems per CTA
#define NTH  288           // 9 warps: warps 0-7 = units 0..63 x 4 colgroups, warp 8 special
#define NU   65            // unit-groups: 50 L1 units + 15 L2 units
#define KL   88            // padded dot length (38+50); L2 uses window base 38 + zero pad
#define KL2  65            // real dot length for L2 (50+15)
#define VP   32            // value-vector pitch (floats) = 128 B
#define VROWS 128          // rows: [0,38)=x, [38,88)=h1, [88,103)=h2, rest zero pad
#define VSZ  (VROWS*VP)    // 4096 floats per buffer

// Shared memory: wP[(k*4+g)*65+u] = (w,w) packed u64, then v[2][128][32] floats
#define WP_U64   (KL*4*NU)            // 22880 u64 = 183040 B
#define SM_V_OFF (WP_U64*8)           // byte offset of v
#define SMEM_BYTES (SM_V_OFF + 2*VSZ*4)   // 215808 B

typedef unsigned long long u64t;

__device__ __forceinline__ u64t pk2(float a, float b){
    u64t d; asm("mov.b64 %0, {%1, %2};" : "=l"(d) : "f"(a), "f"(b)); return d;
}
__device__ __forceinline__ void up2(u64t d, float& a, float& b){
    asm("mov.b64 {%0, %1}, %2;" : "=f"(a), "=f"(b) : "l"(d));
}
__device__ __forceinline__ void fma2(u64t& d, u64t a, u64t b){
    asm("fma.rn.f32x2 %0, %1, %2, %0;" : "+l"(d) : "l"(a), "l"(b));
}

__device__ __forceinline__ float sigf(float x){
    float e = __expf(-x);
    return __fdividef(1.0f, 1.0f + e);
}
__device__ __forceinline__ float tanh_(float x){
    float a = fabsf(x);
    float e = __expf(-2.0f * a);
    float r = __fdividef(1.0f - e, 1.0f + e);
    return copysignf(r, x);
}

__global__ __launch_bounds__(NTH, 1)
void lstm_persist_kernel(const float* __restrict__ x,
                         const float* __restrict__ w_ih1, const float* __restrict__ w_hh1,
                         const float* __restrict__ b_ih1, const float* __restrict__ b_hh1,
                         const float* __restrict__ w_ih2, const float* __restrict__ w_hh2,
                         const float* __restrict__ b_ih2, const float* __restrict__ b_hh2,
                         const float* __restrict__ w_fc,  const float* __restrict__ b_fc,
                         float* __restrict__ out)
{
    extern __shared__ float sm[];
    u64t*  wp   = reinterpret_cast<u64t*>(sm);
    float* vbuf = sm + SM_V_OFF / 4;

    const int tid = threadIdx.x;
    const int b0  = blockIdx.x * NB;

    // ---- Build duplicated weight table: wp[(k*4+g)*NU + u] = (w,w) ----
    for (int idx = tid; idx < WP_U64; idx += NTH){
        int u  = idx % NU;
        int kg = idx / NU;
        int g  = kg & 3, k = kg >> 2;
        float w = 0.0f;
        if (u < 50){                       // L1 unit u, window base 0: [x | h1]
            int row = g * H1c + u;
            w = (k < I1c) ? w_ih1[row*I1c + k] : w_hh1[row*H1c + (k - I1c)];
        } else {                           // L2 unit r, window base 38: [h1 | h2 | pad]
            int r = u - 50, row = g * H2c + r;
            if (k < H1c)            w = w_ih2[row*H1c + k];
            else if (k < KL2)       w = w_hh2[row*H2c + (k - H1c)];
        }
        wp[idx] = pk2(w, w);
    }

    // ---- Zero both v buffers (includes pad rows), then load x(0) ----
    for (int idx = tid; idx < 2*VSZ; idx += NTH) vbuf[idx] = 0.0f;
    __syncthreads();
    for (int idx = tid; idx < NB*I1c; idx += NTH){
        int nb = idx / I1c, i = idx % I1c;
        vbuf[i*VP + nb] = x[((size_t)(b0 + nb) * Tc) * I1c + i];
    }

    // Per-thread roles
    const int u  = tid >> 2;        // unit group (tid<256)
    const int cg = tid & 3;         // batch colgroup (8 batch each)
    const bool isL1 = (u < 50);

    float bias[4];
    if (tid < 256){
        if (isL1){
            #pragma unroll
            for (int g = 0; g < 4; g++) bias[g] = b_ih1[g*H1c + u] + b_hh1[g*H1c + u];
        } else {
            int r = u - 50;
            #pragma unroll
            for (int g = 0; g < 4; g++) bias[g] = b_ih2[g*H2c + r] + b_hh2[g*H2c + r];
        }
    }
    // Warp 8: lane j handles L2 unit 14 for batch j (scalar), plus x prefetch
    float b14[4];
    if (tid >= 256){
        #pragma unroll
        for (int g = 0; g < 4; g++) b14[g] = b_ih2[g*H2c + 14] + b_hh2[g*H2c + 14];
    }

    float cst[8];
    #pragma unroll
    for (int s = 0; s < 8; s++) cst[s] = 0.0f;
    float c14 = 0.0f;

    const int base = isL1 ? 0 : I1c;
    __syncthreads();

    // Iter t: L1 computes step t (reads x(t), h1(t-1)); L2 computes step t-1
    // (reads h1(t-1), h2(t-2)). All writes go to the other buffer vn.
    for (int t = 0; t <= Tc; t++){
        float* vc = vbuf + (t & 1) * VSZ;
        float* vn = vbuf + ((t + 1) & 1) * VSZ;

        if (tid < 256){
            if (isL1 ? (t < Tc) : true){
                u64t acc[4][4];
                #pragma unroll
                for (int g = 0; g < 4; g++)
                    #pragma unroll
                    for (int p = 0; p < 4; p++) acc[g][p] = pk2(bias[g], bias[g]);

                const u64t* vrow = reinterpret_cast<const u64t*>(vc + base*VP) + cg*4;
                const u64t* wrow = wp + u;
                #pragma unroll 4
                for (int k = 0; k < KL; k++){
                    ulonglong2 p0 = *reinterpret_cast<const ulonglong2*>(vrow + (size_t)k*(VP/2));
                    ulonglong2 p1 = *reinterpret_cast<const ulonglong2*>(vrow + (size_t)k*(VP/2) + 2);
                    u64t w0 = wrow[(k*4+0)*NU];
                    u64t w1 = wrow[(k*4+1)*NU];
                    u64t w2 = wrow[(k*4+2)*NU];
                    u64t w3 = wrow[(k*4+3)*NU];
                    fma2(acc[0][0], w0, p0.x); fma2(acc[0][1], w0, p0.y);
                    fma2(acc[0][2], w0, p1.x); fma2(acc[0][3], w0, p1.y);
                    fma2(acc[1][0], w1, p0.x); fma2(acc[1][1], w1, p0.y);
                    fma2(acc[1][2], w1, p1.x); fma2(acc[1][3], w1, p1.y);
                    fma2(acc[2][0], w2, p0.x); fma2(acc[2][1], w2, p0.y);
                    fma2(acc[2][2], w2, p1.x); fma2(acc[2][3], w2, p1.y);
                    fma2(acc[3][0], w3, p0.x); fma2(acc[3][1], w3, p0.y);
                    fma2(acc[3][2], w3, p1.x); fma2(acc[3][3], w3, p1.y);
                }

                if (isL1 || t >= 1){    // L2's step t-1 exists only for t>=1
                    float* hout = isL1 ? (vn + (I1c + u)*VP + cg*8)
                                       : (vn + (88 + (u - 50))*VP + cg*8);
                    #pragma unroll
                    for (int p = 0; p < 4; p++){
                        float i0,i1,f0,f1,g0,g1,o0,o1;
                        up2(acc[0][p], i0, i1);
                        up2(acc[1][p], f0, f1);
                        up2(acc[2][p], g0, g1);
                        up2(acc[3][p], o0, o1);
                        float c0 = fmaf(sigf(f0), cst[2*p  ], sigf(i0)*tanh_(g0));
                        float c1 = fmaf(sigf(f1), cst[2*p+1], sigf(i1)*tanh_(g1));
                        cst[2*p  ] = c0;
                        cst[2*p+1] = c1;
                        hout[2*p  ] = sigf(o0)*tanh_(c0);
                        hout[2*p+1] = sigf(o1)*tanh_(c1);
                    }
                }
            }
        } else {
            // ---- Warp 8: scalar path for L2 unit 14, then x(t+1) prefetch ----
            int j = tid - 256;     // batch index 0..31
            float a0 = b14[0], a1 = b14[1], a2 = b14[2], a3 = b14[3];
            const float* vr  = vc + I1c*VP + j;
            const float* wpf = reinterpret_cast<const float*>(wp);   // lower half of (w,w)
            #pragma unroll 5
            for (int k = 0; k < KL2; k++){
                float v = vr[k*VP];
                a0 = fmaf(wpf[((k*4+0)*NU + 64)*2], v, a0);
                a1 = fmaf(wpf[((k*4+1)*NU + 64)*2], v, a1);
                a2 = fmaf(wpf[((k*4+2)*NU + 64)*2], v, a2);
                a3 = fmaf(wpf[((k*4+3)*NU + 64)*2], v, a3);
            }
            if (t >= 1){
                c14 = fmaf(sigf(a1), c14, sigf(a0)*tanh_(a2));
                vn[(88 + 14)*VP + j] = sigf(a3)*tanh_(c14);
            }
            if (t + 1 < Tc){
                const float* xs = x + ((size_t)(b0 + j) * Tc + (t + 1)) * I1c;
                float* xd = vn + j;
                #pragma unroll
                for (int i = 0; i < I1c; i++) xd[i*VP] = __ldcg(xs + i);
            }
        }
        __syncthreads();
    }

    // ---- FC head: final h2 lives in vbuf[1] rows 88..102 ----
    const float* h2f = vbuf + VSZ + 88*VP;
    for (int q = tid; q < NB*NCc; q += NTH){
        int nb = q / NCc, cls = q % NCc;
        float s = b_fc[cls];
        #pragma unroll
        for (int h = 0; h < H2c; h++)
            s = fmaf(w_fc[cls*H2c + h], h2f[h*VP + nb], s);
        out[(size_t)(b0 + nb)*NCc + cls] = s;
    }
}

extern "C" void kernel_launch(void* const* d_in, const int* in_sizes, int n_in,
                              void* d_out, int out_size)
{
    const float* x     = (const float*)d_in[0];
    const float* w_ih1 = (const float*)d_in[1];
    const float* w_hh1 = (const float*)d_in[2];
    const float* b_ih1 = (const float*)d_in[3];
    const float* b_hh1 = (const float*)d_in[4];
    const float* w_ih2 = (const float*)d_in[5];
    const float* w_hh2 = (const float*)d_in[6];
    const float* b_ih2 = (const float*)d_in[7];
    const float* b_hh2 = (const float*)d_in[8];
    const float* w_fc  = (const float*)d_in[9];
    const float* b_fc  = (const float*)d_in[10];
    float* out = (float*)d_out;

    cudaFuncSetAttribute(lstm_persist_kernel,
                         cudaFuncAttributeMaxDynamicSharedMemorySize, SMEM_BYTES);

    const int grid = Bc / NB;   // 128 CTAs -> one wave
    lstm_persist_kernel<<<grid, NTH, SMEM_BYTES>>>(
        x, w_ih1, w_hh1, b_ih1, b_hh1,
        w_ih2, w_hh2, b_ih2, b_hh2, w_fc, b_fc, out);
}